// round 5
// baseline (speedup 1.0000x reference)
#include <cuda_runtime.h>
#include <cstdint>

// TranVectorQuantizer: latent [32768, 8, 32] f32, codebook [128, 32] f32
// Outputs (f32, concatenated): policy[8.4M] | quantized[8.4M] | codebook_set[134.2M]
//
// codebook_set (512 MB = 84% of traffic) is 32768 replicas of the 16 KB smem
// codebook tile -> issued as cp.async.bulk shared->global (TMA) copies, ~108
// per block, enqueued once up front by threads 0..107. Zero ongoing SMSP cost;
// TMA drains concurrently with compute. All 8 warps/block run the FFMA2
// argmin (bit-exact vs XLA, rel_err 0.0 in rounds 1-4) with dynamic chunk
// stealing for perfect balance.

#define KCODES 128
#define DDIM 32
#define NGRID 304            // 2 CTAs x 152 SMs
#define NBATCH 32768
#define NCHUNKS 512          // 262144 vectors / 512 per chunk
#define PERBLK ((NBATCH + NGRID - 1) / NGRID)   // 108 TMA copies per block

__device__ unsigned int g_chunk;

__global__ void vq_init_kernel() { g_chunk = 0u; }

__device__ __forceinline__ float2 ffma2(float2 a, float2 b, float2 c) {
    float2 d;
    asm("fma.rn.f32x2 %0, %1, %2, %3;"
        : "=l"(reinterpret_cast<unsigned long long&>(d))
        : "l"(reinterpret_cast<unsigned long long&>(a)),
          "l"(reinterpret_cast<unsigned long long&>(b)),
          "l"(reinterpret_cast<unsigned long long&>(c)));
    return d;
}

__device__ __forceinline__ uint32_t smem_u32(const void* p) {
    uint32_t a;
    asm("{ .reg .u64 t; cvta.to.shared.u64 t, %1; cvt.u32.u64 %0, t; }"
        : "=r"(a) : "l"(p));
    return a;
}

__global__ void __launch_bounds__(256, 2) vq_kernel(
    const float* __restrict__ latent,
    const float* __restrict__ codebook,
    float* __restrict__ out_policy,
    float* __restrict__ out_quant,
    float* __restrict__ out_cbset)
{
    __shared__ __align__(128) float cbs[KCODES * DDIM];   // raw codebook, 16 KB
    __shared__ float2 cbp[KCODES / 2][DDIM];              // k-pair interleaved, 16 KB
    __shared__ float2 cnp[KCODES / 2];                    // norms, k-pair packed
    __shared__ unsigned s_chunk;

    const int t = threadIdx.x;
    const int bid = blockIdx.x;

    // ─── stage codebook into smem ────────────────────────────────────────
    {
        const float4* src = (const float4*)codebook;
        float4* dst = (float4*)cbs;
#pragma unroll
        for (int j = 0; j < 4; j++) dst[t + j * 256] = src[t + j * 256];
    }
    __syncthreads();

    // pack: cbp[p][i] = (cb[2p][i], cb[2p+1][i]); norms
#pragma unroll
    for (int j = 0; j < 8; j++) {
        int q = t + j * 256;            // 0..2047
        int p = q >> 5, i = q & 31;
        cbp[p][i] = make_float2(cbs[(2 * p) * DDIM + i], cbs[(2 * p + 1) * DDIM + i]);
    }
    if (t < KCODES) {
        float s = 0.f;
#pragma unroll
        for (int i = 0; i < DDIM; i++) {
            float c = cbs[t * DDIM + i];
            s = fmaf(c, c, s);
        }
        ((float*)cnp)[t] = s;           // cnp[p] = (cn[2p], cn[2p+1])
    }
    __syncthreads();

    // ─── enqueue this block's codebook_set replicas via TMA bulk stores ──
    // threads 0..PERBLK-1 each issue one 16 KB shared->global bulk copy.
    bool issued = false;
    if (t < PERBLK) {
        long long b = (long long)bid * PERBLK + t;
        if (b < NBATCH) {
            asm volatile("fence.proxy.async.shared::cta;" ::: "memory");
            uint32_t s = smem_u32(cbs);
            float* dst = out_cbset + b * (KCODES * DDIM);
            asm volatile(
                "cp.async.bulk.global.shared::cta.bulk_group [%0], [%1], %2;"
                :: "l"(dst), "r"(s), "r"(KCODES * DDIM * 4) : "memory");
            asm volatile("cp.async.bulk.commit_group;" ::: "memory");
            issued = true;
        }
    }

    // ─── compute: dynamic chunk stealing, FFMA2 argmin ───────────────────
    for (;;) {
        __syncthreads();
        if (t == 0) s_chunk = atomicAdd(&g_chunk, 1u);
        __syncthreads();
        unsigned c = s_chunk;
        if (c >= NCHUNKS) break;

        const long long n0 = (long long)c * 512 + t;   // vector 0
        const long long n1 = n0 + 256;                 // vector 1

        // load both vectors; duplicate components into f32x2 pairs
        float2 xa[DDIM], xb[DDIM];
        {
            const float4* la = (const float4*)(latent + n0 * DDIM);
            const float4* lb = (const float4*)(latent + n1 * DDIM);
#pragma unroll
            for (int j = 0; j < 8; j++) {
                float4 v = __ldcs(&la[j]);
                xa[4 * j + 0] = make_float2(v.x, v.x);
                xa[4 * j + 1] = make_float2(v.y, v.y);
                xa[4 * j + 2] = make_float2(v.z, v.z);
                xa[4 * j + 3] = make_float2(v.w, v.w);
                float4 w = __ldcs(&lb[j]);
                xb[4 * j + 0] = make_float2(w.x, w.x);
                xb[4 * j + 1] = make_float2(w.y, w.y);
                xb[4 * j + 2] = make_float2(w.z, w.z);
                xb[4 * j + 3] = make_float2(w.w, w.w);
            }
        }

        // ||x||^2 — sequential fma chains (bit-match reference; DO NOT reorder)
        float xx0 = 0.f, xx1 = 0.f;
#pragma unroll
        for (int i = 0; i < DDIM; i++) xx0 = fmaf(xa[i].x, xa[i].x, xx0);
#pragma unroll
        for (int i = 0; i < DDIM; i++) xx1 = fmaf(xb[i].x, xb[i].x, xx1);

        // argmin over 64 k-pairs; each packed lane is a sequential fp32 chain
        float best0 = __int_as_float(0x7f800000);
        float best1 = __int_as_float(0x7f800000);
        int bk0 = 0, bk1 = 0;
#pragma unroll 1
        for (int p = 0; p < KCODES / 2; p++) {
            float2 dot0 = make_float2(0.f, 0.f);
            float2 dot1 = make_float2(0.f, 0.f);
            const float4* r = (const float4*)cbp[p];   // 16 x float4
#pragma unroll
            for (int j = 0; j < 16; j++) {
                float4 a = r[j];
                float2 cl = make_float2(a.x, a.y);     // dim 2j
                float2 ch = make_float2(a.z, a.w);     // dim 2j+1
                dot0 = ffma2(xa[2 * j],     cl, dot0);
                dot0 = ffma2(xa[2 * j + 1], ch, dot0);
                dot1 = ffma2(xb[2 * j],     cl, dot1);
                dot1 = ffma2(xb[2 * j + 1], ch, dot1);
            }
            float2 cn2 = cnp[p];
            float d00 = (xx0 + cn2.x) - 2.0f * dot0.x;
            float d01 = (xx0 + cn2.y) - 2.0f * dot0.y;
            float d10 = (xx1 + cn2.x) - 2.0f * dot1.x;
            float d11 = (xx1 + cn2.y) - 2.0f * dot1.y;
            if (d00 < best0) { best0 = d00; bk0 = 2 * p; }
            if (d01 < best0) { best0 = d01; bk0 = 2 * p + 1; }
            if (d10 < best1) { best1 = d10; bk1 = 2 * p; }
            if (d11 < best1) { best1 = d11; bk1 = 2 * p + 1; }
        }

        // epilogue: quantized + policy (policy = x + (q - x), fp32)
        {
            float4* qo = (float4*)(out_quant + n0 * DDIM);
            float4* po = (float4*)(out_policy + n0 * DDIM);
            const float4* cq = (const float4*)(cbs + bk0 * DDIM);
#pragma unroll
            for (int j = 0; j < 8; j++) {
                float4 q = cq[j];
                float4 p4;
                p4.x = xa[4 * j + 0].x + (q.x - xa[4 * j + 0].x);
                p4.y = xa[4 * j + 1].x + (q.y - xa[4 * j + 1].x);
                p4.z = xa[4 * j + 2].x + (q.z - xa[4 * j + 2].x);
                p4.w = xa[4 * j + 3].x + (q.w - xa[4 * j + 3].x);
                __stcs(&qo[j], q);
                __stcs(&po[j], p4);
            }
        }
        {
            float4* qo = (float4*)(out_quant + n1 * DDIM);
            float4* po = (float4*)(out_policy + n1 * DDIM);
            const float4* cq = (const float4*)(cbs + bk1 * DDIM);
#pragma unroll
            for (int j = 0; j < 8; j++) {
                float4 q = cq[j];
                float4 p4;
                p4.x = xb[4 * j + 0].x + (q.x - xb[4 * j + 0].x);
                p4.y = xb[4 * j + 1].x + (q.y - xb[4 * j + 1].x);
                p4.z = xb[4 * j + 2].x + (q.z - xb[4 * j + 2].x);
                p4.w = xb[4 * j + 3].x + (q.w - xb[4 * j + 3].x);
                __stcs(&qo[j], q);
                __stcs(&po[j], p4);
            }
        }
    }

    // drain this thread's bulk stores before exit (smem must stay live)
    if (issued) {
        asm volatile("cp.async.bulk.wait_group 0;" ::: "memory");
    }
}

extern "C" void kernel_launch(void* const* d_in, const int* in_sizes, int n_in,
                              void* d_out, int out_size) {
    const float* latent = (const float*)d_in[0];
    const float* codebook = (const float*)d_in[1];

    const long long Nvec = (long long)in_sizes[0] / DDIM;   // 262144

    float* out_policy = (float*)d_out;
    float* out_quant = out_policy + Nvec * DDIM;
    float* out_cbset = out_quant + Nvec * DDIM;

    vq_init_kernel<<<1, 1>>>();
    vq_kernel<<<NGRID, 256>>>(latent, codebook, out_policy, out_quant, out_cbset);
}

// round 6
// speedup vs baseline: 1.0298x; 1.0298x over previous
#include <cuda_runtime.h>
#include <cstdint>

// TranVectorQuantizer: latent [32768, 8, 32] f32, codebook [128, 32] f32
// Outputs (f32, concatenated): policy[8.4M] | quantized[8.4M] | codebook_set[134.2M]
//
// One block type, warp-specialized: warps 0-5 compute the argmin (vector-lane
// packed FFMA2: lanes of f32x2 = two latent vectors, codes duplicated in smem),
// warps 6-7 stream the 512 MB codebook_set broadcast from smem with STG.cs.
// Compute warps join the store stream when compute work is exhausted.
// Both roles use global atomic work-stealing (4096 units each).
// Distance chains are exact sequential fp32 fma -> bit-identical argmin vs XLA.

#define KCODES 128
#define DDIM 32
#define NGRID 304            // 2 CTAs x 152 SMs
#define CUNITS 4096          // compute units: 64 vectors each (262144/64)
#define SUNITS 4096          // store units: 8 batch copies each (32768/8)

__device__ unsigned g_cchunk;
__device__ unsigned g_schunk;

__global__ void vq_init_kernel() { g_cchunk = 0u; g_schunk = 0u; }

__device__ __forceinline__ float2 ffma2(float2 a, float2 b, float2 c) {
    float2 d;
    asm("fma.rn.f32x2 %0, %1, %2, %3;"
        : "=l"(reinterpret_cast<unsigned long long&>(d))
        : "l"(reinterpret_cast<unsigned long long&>(a)),
          "l"(reinterpret_cast<unsigned long long&>(b)),
          "l"(reinterpret_cast<unsigned long long&>(c)));
    return d;
}

struct SmemLayout {
    float  cbs[KCODES * DDIM];          // raw codebook (row-major), 16 KB
    float2 cbd[KCODES][DDIM];           // duplicated codes (c,c), 32 KB
    float  cn[KCODES];                  // code norms
};

__device__ __forceinline__ void store_stream(const SmemLayout* sm, float* out_cbset,
                                             int lane) {
    for (;;) {
        unsigned u;
        if (lane == 0) u = atomicAdd(&g_schunk, 1u);
        u = __shfl_sync(0xFFFFFFFFu, u, 0);
        if (u >= SUNITS) break;
        const float4* src = (const float4*)sm->cbs;
#pragma unroll 1
        for (int c = 0; c < 8; c++) {
            long long b = (long long)u * 8 + c;
            float4* dst = (float4*)(out_cbset + b * (KCODES * DDIM));
#pragma unroll
            for (int j = 0; j < 32; j++) {
                int idx = j * 32 + lane;
                __stcs(&dst[idx], src[idx]);
            }
        }
    }
}

__global__ void __launch_bounds__(256, 2) vq_kernel(
    const float* __restrict__ latent,
    const float* __restrict__ codebook,
    float* __restrict__ out_policy,
    float* __restrict__ out_quant,
    float* __restrict__ out_cbset)
{
    __shared__ SmemLayout sm;

    const int t = threadIdx.x;
    const int wid = t >> 5;
    const int lane = t & 31;

    // ─── stage codebook, duplicated pack, norms ──────────────────────────
    {
        const float4* src = (const float4*)codebook;
        float4* dst = (float4*)sm.cbs;
#pragma unroll
        for (int j = 0; j < 4; j++) dst[t + j * 256] = src[t + j * 256];
    }
    __syncthreads();
#pragma unroll
    for (int j = 0; j < 16; j++) {
        int q = t + j * 256;            // 0..4095
        int k = q >> 5, i = q & 31;
        float c = sm.cbs[k * DDIM + i];
        sm.cbd[k][i] = make_float2(c, c);
    }
    if (t < KCODES) {
        float s = 0.f;
#pragma unroll
        for (int i = 0; i < DDIM; i++) {
            float c = sm.cbs[t * DDIM + i];
            s = fmaf(c, c, s);
        }
        sm.cn[t] = s;
    }
    __syncthreads();

    if (wid >= 6) {
        // ─── STORE WARPS ─────────────────────────────────────────────────
        store_stream(&sm, out_cbset, lane);
        return;
    }

    // ─── COMPUTE WARPS: warp-level work stealing ─────────────────────────
    for (;;) {
        unsigned u;
        if (lane == 0) u = atomicAdd(&g_cchunk, 1u);
        u = __shfl_sync(0xFFFFFFFFu, u, 0);
        if (u >= CUNITS) break;

        const int n0 = (int)u * 64 + lane;   // vector 0
        const int n1 = n0 + 32;              // vector 1

        // load both vectors packed: xp[i] = (xa_i, xb_i)
        float2 xp[DDIM];
        {
            const float4* la = (const float4*)(latent + (long long)n0 * DDIM);
            const float4* lb = (const float4*)(latent + (long long)n1 * DDIM);
#pragma unroll
            for (int j = 0; j < 8; j++) {
                float4 v = __ldcs(&la[j]);
                float4 w = __ldcs(&lb[j]);
                xp[4 * j + 0] = make_float2(v.x, w.x);
                xp[4 * j + 1] = make_float2(v.y, w.y);
                xp[4 * j + 2] = make_float2(v.z, w.z);
                xp[4 * j + 3] = make_float2(v.w, w.w);
            }
        }

        // ||x||^2 for both lanes — sequential fp32 chains (bit-exact; DO NOT reorder)
        float2 xx2 = make_float2(0.f, 0.f);
#pragma unroll
        for (int i = 0; i < DDIM; i++) xx2 = ffma2(xp[i], xp[i], xx2);

        // argmin over 128 codes, k unrolled by 2 (two chains for ILP).
        float best0 = __int_as_float(0x7f800000);
        float best1 = __int_as_float(0x7f800000);
        int bk0 = 0, bk1 = 0;
#pragma unroll 2
        for (int k = 0; k < KCODES; k += 2) {
            float2 dotA = make_float2(0.f, 0.f);
            float2 dotB = make_float2(0.f, 0.f);
            const float4* ra = (const float4*)sm.cbd[k];       // (c2j,c2j,c2j+1,c2j+1)
            const float4* rb = (const float4*)sm.cbd[k + 1];
#pragma unroll
            for (int j = 0; j < 16; j++) {
                float4 a = ra[j];
                float4 b = rb[j];
                dotA = ffma2(xp[2 * j],     make_float2(a.x, a.y), dotA);
                dotA = ffma2(xp[2 * j + 1], make_float2(a.z, a.w), dotA);
                dotB = ffma2(xp[2 * j],     make_float2(b.x, b.y), dotB);
                dotB = ffma2(xp[2 * j + 1], make_float2(b.z, b.w), dotB);
            }
            float cnA = sm.cn[k], cnB = sm.cn[k + 1];
            float d00 = (xx2.x + cnA) - 2.0f * dotA.x;   // v0, code k
            float d10 = (xx2.y + cnA) - 2.0f * dotA.y;   // v1, code k
            float d01 = (xx2.x + cnB) - 2.0f * dotB.x;   // v0, code k+1
            float d11 = (xx2.y + cnB) - 2.0f * dotB.y;   // v1, code k+1
            if (d00 < best0) { best0 = d00; bk0 = k; }
            if (d01 < best0) { best0 = d01; bk0 = k + 1; }
            if (d10 < best1) { best1 = d10; bk1 = k; }
            if (d11 < best1) { best1 = d11; bk1 = k + 1; }
        }

        // epilogue: quantized + policy (policy = x + (q - x), exact fp32)
        {
            float4* qo = (float4*)(out_quant + (long long)n0 * DDIM);
            float4* po = (float4*)(out_policy + (long long)n0 * DDIM);
            const float4* cq = (const float4*)(sm.cbs + bk0 * DDIM);
#pragma unroll
            for (int j = 0; j < 8; j++) {
                float4 q = cq[j];
                float4 p4;
                p4.x = xp[4 * j + 0].x + (q.x - xp[4 * j + 0].x);
                p4.y = xp[4 * j + 1].x + (q.y - xp[4 * j + 1].x);
                p4.z = xp[4 * j + 2].x + (q.z - xp[4 * j + 2].x);
                p4.w = xp[4 * j + 3].x + (q.w - xp[4 * j + 3].x);
                __stcs(&qo[j], q);
                __stcs(&po[j], p4);
            }
        }
        {
            float4* qo = (float4*)(out_quant + (long long)n1 * DDIM);
            float4* po = (float4*)(out_policy + (long long)n1 * DDIM);
            const float4* cq = (const float4*)(sm.cbs + bk1 * DDIM);
#pragma unroll
            for (int j = 0; j < 8; j++) {
                float4 q = cq[j];
                float4 p4;
                p4.x = xp[4 * j + 0].y + (q.x - xp[4 * j + 0].y);
                p4.y = xp[4 * j + 1].y + (q.y - xp[4 * j + 1].y);
                p4.z = xp[4 * j + 2].y + (q.z - xp[4 * j + 2].y);
                p4.w = xp[4 * j + 3].y + (q.w - xp[4 * j + 3].y);
                __stcs(&qo[j], q);
                __stcs(&po[j], p4);
            }
        }
    }

    // compute exhausted -> help drain the broadcast store stream
    store_stream(&sm, out_cbset, lane);
}

extern "C" void kernel_launch(void* const* d_in, const int* in_sizes, int n_in,
                              void* d_out, int out_size) {
    const float* latent = (const float*)d_in[0];
    const float* codebook = (const float*)d_in[1];

    const long long Nvec = (long long)in_sizes[0] / DDIM;   // 262144

    float* out_policy = (float*)d_out;
    float* out_quant = out_policy + Nvec * DDIM;
    float* out_cbset = out_quant + Nvec * DDIM;

    vq_init_kernel<<<1, 1>>>();
    vq_kernel<<<NGRID, 256>>>(latent, codebook, out_policy, out_quant, out_cbset);
}